// round 16
// baseline (speedup 1.0000x reference)
#include <cuda_runtime.h>
#include <cuda_fp16.h>
#include <mma.h>
#include <math.h>

using namespace nvcuda;

#define NN 50000
#define EE 800000
#define ETOT (EE + NN)
#define NH 4
#define NEG 0.2f
#define EPSV 1e-16f
#define SCB 1024
#define NBLK ((NN + SCB - 1) / SCB)   // 49
#define FLAGB 0x40000000

// ---------------- scratch (device globals; no allocation) ----------------
// NOTE: never pass these as kernel args from host code (host shadow symbol bug).
__device__ __half g_h1h[NN * 64];   // layer1 features fp16 (gather-only)
__device__ __half g_h2h[NN * 32];   // layer2 features fp16 (separate: no race with layer1 reads)
__device__ float  g_als[NN * NH];   // layer1 logits
__device__ float  g_ald[NN * NH];
__device__ float  g_als2[NN * NH];  // layer2 logits (separate buffers)
__device__ float  g_ald2[NN * NH];
__device__ int    g_cnt[NN];        // zeroed at start; re-zeroed by k_scan each run
__device__ int    g_off[NN + 1];
__device__ int    g_cur[NN];
__device__ int    g_esrc[ETOT];
__device__ int    g_bsum[NBLK];     // lookback aggregates; re-zeroed by k_fill each run

__device__ __forceinline__ int detect_is64_block(const int* __restrict__ ei32, int* s_flag) {
    if (threadIdx.x == 0) {
        int all0 = 1;
        for (int j = 0; j < 32; j++)
            if (ei32[2 * j + 1] != 0) { all0 = 0; break; }
        *s_flag = all0;
    }
    __syncthreads();
    return *s_flag;
}

// ---------------- dst histogram, 2 edges/thread (full-chip) ----------------
__global__ void k_build_hist(const int* __restrict__ ei32, int E, int Etot) {
    __shared__ int s64;
    int is64 = detect_is64_block(ei32, &s64);
    int e = (blockIdx.x * blockDim.x + threadIdx.x) * 2;
    if (e >= Etot) return;
    int d0, d1;
    if (e < E) {
        if (is64) { int4 v = *reinterpret_cast<const int4*>(&ei32[2 * (E + e)]); d0 = v.x; d1 = v.z; }
        else      { int2 v = *reinterpret_cast<const int2*>(&ei32[E + e]);       d0 = v.x; d1 = v.y; }
    } else { d0 = e - E; d1 = e + 1 - E; }
    atomicAdd(&g_cnt[d0], 1);
    atomicAdd(&g_cnt[d1], 1);
}

// ---------------- single-pass decoupled-lookback exclusive scan ----------------
__global__ void k_scan(int n, int Etot) {
    __shared__ int ws[32];
    __shared__ int s_pre;
    int t = threadIdx.x;
    int bid = blockIdx.x;
    int i = bid * SCB + t;
    int v = (i < n) ? g_cnt[i] : 0;
    int x = v;
#pragma unroll
    for (int ofs = 1; ofs < 32; ofs <<= 1) {
        int u = __shfl_up_sync(0xffffffffu, x, ofs);
        if ((t & 31) >= ofs) x += u;
    }
    if ((t & 31) == 31) ws[t >> 5] = x;
    __syncthreads();
    if (t < 32) {
        int y = ws[t];
#pragma unroll
        for (int ofs = 1; ofs < 32; ofs <<= 1) {
            int u = __shfl_up_sync(0xffffffffu, y, ofs);
            if (t >= ofs) y += u;
        }
        ws[t] = y;
    }
    __syncthreads();
    int base = (t >= 32) ? ws[(t >> 5) - 1] : 0;
    int incl = x + base;
    if (t == 0)
        atomicExch(&g_bsum[bid], ws[31] | FLAGB);
    if (t < 32) {
        int pre = 0;
        for (int b0 = 0; b0 < bid; b0 += 32) {
            int j = b0 + t;
            int vv = 0;
            if (j < bid) {
                while (((vv = atomicAdd(&g_bsum[j], 0)) & FLAGB) == 0) { }
                vv &= ~FLAGB;
            }
#pragma unroll
            for (int ofs = 16; ofs; ofs >>= 1)
                vv += __shfl_xor_sync(0xffffffffu, vv, ofs);
            pre += vv;
        }
        if (t == 0) s_pre = pre;
    }
    __syncthreads();
    int off = incl - v + s_pre;
    if (i < n) {
        g_off[i] = off;
        g_cur[i] = off;
        g_cnt[i] = 0;
    }
    if (i == 0) g_off[n] = Etot;
}

// ---------------- bucket-fill, 2 edges/thread (full-chip, + g_bsum reset) ----------------
__global__ void k_fill(const int* __restrict__ ei32, int E, int Etot) {
    __shared__ int s64;
    int is64 = detect_is64_block(ei32, &s64);
    if (blockIdx.x == 0 && threadIdx.x < NBLK) g_bsum[threadIdx.x] = 0;
    int e = (blockIdx.x * blockDim.x + threadIdx.x) * 2;
    if (e >= Etot) return;
    int s0, s1, d0, d1;
    if (e < E) {
        if (is64) {
            int4 sv = *reinterpret_cast<const int4*>(&ei32[2 * e]);
            int4 dv = *reinterpret_cast<const int4*>(&ei32[2 * (E + e)]);
            s0 = sv.x; s1 = sv.z; d0 = dv.x; d1 = dv.z;
        } else {
            int2 sv = *reinterpret_cast<const int2*>(&ei32[e]);
            int2 dv = *reinterpret_cast<const int2*>(&ei32[E + e]);
            s0 = sv.x; s1 = sv.y; d0 = dv.x; d1 = dv.y;
        }
    } else { s0 = d0 = e - E; s1 = d1 = e + 1 - E; }
    int p0 = atomicAdd(&g_cur[d0], 1);
    g_esrc[p0] = s0;
    int p1 = atomicAdd(&g_cur[d1], 1);
    g_esrc[p1] = s1;
}

// ---------------- gemm1 (R13 config): wmma fp16, 128 rows, 256 thr, KT=64 chunks ----------------
// g_h1h <- fp16(x @ W1); fused per-head logits -> g_als/g_ald.
__global__ void k_gemm1(const float* __restrict__ A_arg,
                        const float* __restrict__ W,
                        const float* __restrict__ asrc,
                        const float* __restrict__ adst, int n) {
    const int KTOT = 128, COLS = 64;
    const int KT  = 64;
    const int NCH = 2;
    const int LDA = KT + 8;            // 72
    const int LDB = COLS + 8;          // 72
    const int LDC = COLS + 8;          // 72
    const int NF  = COLS / 16;         // 4
    const int ABBYTES = 128 * LDA * 2 + KTOT * LDB * 2;   // 36864
    const int CBYTES  = 128 * LDC * 4;                    // 36864
    __shared__ __align__(16) char sraw[ABBYTES > CBYTES ? ABBYTES : CBYTES];
    __half* As = reinterpret_cast<__half*>(sraw);
    __half* Bs = reinterpret_cast<__half*>(sraw + 128 * LDA * 2);
    float*  Cs = reinterpret_cast<float*>(sraw);

    int tid = threadIdx.x;
    int w = tid >> 5;
    int rbase = blockIdx.x * 128;

    // load full W (128 x 64) fp32 -> fp16
    const int B4 = KTOT * COLS / 4;
#pragma unroll
    for (int j = 0; j < (B4 + 255) / 256; j++) {
        int idx = tid + j * 256;
        if (idx < B4) {
            int row = idx / (COLS / 4), c4 = idx % (COLS / 4);
            float4 v = *reinterpret_cast<const float4*>(&W[row * COLS + c4 * 4]);
            __half2 h0 = __floats2half2_rn(v.x, v.y);
            __half2 h1 = __floats2half2_rn(v.z, v.w);
            uint2 u;
            u.x = *reinterpret_cast<unsigned*>(&h0);
            u.y = *reinterpret_cast<unsigned*>(&h1);
            *reinterpret_cast<uint2*>(&Bs[row * LDB + c4 * 4]) = u;
        }
    }

    wmma::fragment<wmma::accumulator, 16, 16, 16, float> c[NF];
#pragma unroll
    for (int j = 0; j < NF; j++) wmma::fill_fragment(c[j], 0.f);

#pragma unroll
    for (int ch = 0; ch < NCH; ch++) {
        __syncthreads();
        const int A4 = 128 * KT / 4;
#pragma unroll
        for (int j = 0; j < A4 / 256; j++) {
            int idx = tid + j * 256;
            int row = idx / (KT / 4), k4 = idx % (KT / 4);
            int rg = rbase + row;
            if (rg >= n) rg = n - 1;
            float4 v = *reinterpret_cast<const float4*>(&A_arg[rg * KTOT + ch * KT + k4 * 4]);
            __half2 h0 = __floats2half2_rn(v.x, v.y);
            __half2 h1 = __floats2half2_rn(v.z, v.w);
            uint2 u;
            u.x = *reinterpret_cast<unsigned*>(&h0);
            u.y = *reinterpret_cast<unsigned*>(&h1);
            *reinterpret_cast<uint2*>(&As[row * LDA + k4 * 4]) = u;
        }
        __syncthreads();
#pragma unroll
        for (int k0 = 0; k0 < KT; k0 += 16) {
            wmma::fragment<wmma::matrix_a, 16, 16, 16, __half, wmma::row_major> a;
            wmma::load_matrix_sync(a, &As[w * 16 * LDA + k0], LDA);
#pragma unroll
            for (int j = 0; j < NF; j++) {
                wmma::fragment<wmma::matrix_b, 16, 16, 16, __half, wmma::row_major> b;
                wmma::load_matrix_sync(b, &Bs[(ch * KT + k0) * LDB + j * 16], LDB);
                wmma::mma_sync(c[j], a, b, c[j]);
            }
        }
    }
    __syncthreads();
#pragma unroll
    for (int j = 0; j < NF; j++)
        wmma::store_matrix_sync(&Cs[w * 16 * LDC + j * 16], c[j], LDC, wmma::mem_row_major);
    __syncthreads();

    // epilogue: fp16 store + fused logits
    const int CG  = COLS / 4;            // 16
    const int RPT = 128 / (256 / CG);    // 8
    const int TXH = 4;                   // C=16 -> 4 tx lanes per head
    int tx = tid % CG, ty = tid / CG;
    float4 sa = *reinterpret_cast<const float4*>(&asrc[tx * 4]);
    float4 da = *reinterpret_cast<const float4*>(&adst[tx * 4]);
    int h = tx / TXH;
#pragma unroll
    for (int i = 0; i < RPT; i++) {
        int row = ty * RPT + i;
        int r = rbase + row;
        float4 acc = *reinterpret_cast<const float4*>(&Cs[row * LDC + tx * 4]);
        float ps = acc.x * sa.x + acc.y * sa.y + acc.z * sa.z + acc.w * sa.w;
        float pd = acc.x * da.x + acc.y * da.y + acc.z * da.z + acc.w * da.w;
#pragma unroll
        for (int ofs = 1; ofs < TXH; ofs <<= 1) {
            ps += __shfl_xor_sync(0xffffffffu, ps, ofs);
            pd += __shfl_xor_sync(0xffffffffu, pd, ofs);
        }
        if (r < n) {
            __half2 ha = __floats2half2_rn(acc.x, acc.y);
            __half2 hb = __floats2half2_rn(acc.z, acc.w);
            uint2 u;
            u.x = *reinterpret_cast<unsigned*>(&ha);
            u.y = *reinterpret_cast<unsigned*>(&hb);
            *reinterpret_cast<uint2*>(&g_h1h[r * COLS + tx * 4]) = u;
            if ((tx & (TXH - 1)) == 0) {
                g_als[r * 4 + h] = ps;
                g_ald[r * 4 + h] = pd;
            }
        }
    }
}

// ---------------- FUSED agg1 + gemm2 ----------------
// Block = 256 thr handles 128 dst nodes: 16 warp-per-node agg passes write relu'd
// fp16 rows straight into the wmma A tile; then mma with W2 and gemm2 epilogue
// writing g_h2h + g_als2/g_ald2 (separate buffers: layer1 arrays still being read
// concurrently by other blocks).
__global__ void k_agg1_gemm2(const float* __restrict__ W2,
                             const float* __restrict__ b1,
                             const float* __restrict__ asrc2,
                             const float* __restrict__ adst2, int n) {
    const int LDA = 72;                // A: 128 x 64 halves (stride 72)
    const int LDB = 40;                // B: 64 x 32 halves
    const int LDC = 40;                // C: 128 x 32 floats
    const int NF  = 2;
    const int ABBYTES = 128 * LDA * 2 + 64 * LDB * 2;   // 18432 + 5120 = 23552
    const int CBYTES  = 128 * LDC * 4;                  // 20480
    __shared__ __align__(16) char sraw[ABBYTES > CBYTES ? ABBYTES : CBYTES];
    __half* As = reinterpret_cast<__half*>(sraw);
    __half* Bs = reinterpret_cast<__half*>(sraw + 128 * LDA * 2);
    float*  Cs = reinterpret_cast<float*>(sraw);

    int tid = threadIdx.x;
    int wid = tid >> 5;
    int lane = tid & 31;
    int rbase = blockIdx.x * 128;

    // load W2 (64 x 32) fp32 -> fp16
#pragma unroll
    for (int j = 0; j < 2; j++) {
        int idx = tid + j * 256;
        int row = idx / 8, c4 = idx % 8;
        float4 v = *reinterpret_cast<const float4*>(&W2[row * 32 + c4 * 4]);
        __half2 h0 = __floats2half2_rn(v.x, v.y);
        __half2 h1 = __floats2half2_rn(v.z, v.w);
        uint2 u;
        u.x = *reinterpret_cast<unsigned*>(&h0);
        u.y = *reinterpret_cast<unsigned*>(&h1);
        *reinterpret_cast<uint2*>(&Bs[row * LDB + c4 * 4]) = u;
    }

    // agg phase: warp per node, 16 passes. LPE=8 lanes x 8 ch; SUBS=4 edges in flight.
    int sub = lane >> 3;
    int l = lane & 7;
    int h = l >> 1;                     // C=16 -> head per channel-octet
    float4 bb0 = reinterpret_cast<const float4*>(b1)[l * 2];
    float4 bb1 = reinterpret_cast<const float4*>(b1)[l * 2 + 1];
    for (int p = 0; p < 16; p++) {
        int row = p * 8 + wid;
        int d = rbase + row;
        float a0 = 0.f, a1 = 0.f, a2 = 0.f, a3 = 0.f;
        float a4 = 0.f, a5 = 0.f, a6 = 0.f, a7 = 0.f;
        float esum = 0.f;
        if (d < n) {
            float ald_v = g_ald[d * 4 + h];
            int off0 = g_off[d], off1 = g_off[d + 1];
            for (int i = off0 + sub; i < off1; i += 4) {
                int s = g_esrc[i];
                float lg = g_als[s * 4 + h] + ald_v;
                lg = (lg >= 0.f) ? lg : NEG * lg;
                float ev = __expf(lg);
                esum += ev;
                uint4 raw = *reinterpret_cast<const uint4*>(&g_h1h[s * 64 + l * 8]);
                float2 f0 = __half22float2(*reinterpret_cast<__half2*>(&raw.x));
                float2 f1 = __half22float2(*reinterpret_cast<__half2*>(&raw.y));
                float2 f2 = __half22float2(*reinterpret_cast<__half2*>(&raw.z));
                float2 f3 = __half22float2(*reinterpret_cast<__half2*>(&raw.w));
                a0 = fmaf(ev, f0.x, a0); a1 = fmaf(ev, f0.y, a1);
                a2 = fmaf(ev, f1.x, a2); a3 = fmaf(ev, f1.y, a3);
                a4 = fmaf(ev, f2.x, a4); a5 = fmaf(ev, f2.y, a5);
                a6 = fmaf(ev, f3.x, a6); a7 = fmaf(ev, f3.y, a7);
            }
        }
#pragma unroll
        for (int ofs = 8; ofs < 32; ofs <<= 1) {
            a0 += __shfl_xor_sync(0xffffffffu, a0, ofs);
            a1 += __shfl_xor_sync(0xffffffffu, a1, ofs);
            a2 += __shfl_xor_sync(0xffffffffu, a2, ofs);
            a3 += __shfl_xor_sync(0xffffffffu, a3, ofs);
            a4 += __shfl_xor_sync(0xffffffffu, a4, ofs);
            a5 += __shfl_xor_sync(0xffffffffu, a5, ofs);
            a6 += __shfl_xor_sync(0xffffffffu, a6, ofs);
            a7 += __shfl_xor_sync(0xffffffffu, a7, ofs);
            esum += __shfl_xor_sync(0xffffffffu, esum, ofs);
        }
        if (sub == 0) {
            uint4 u;
            if (d < n) {
                float inv = 1.f / (esum + EPSV);
                __half2 p0 = __floats2half2_rn(fmaxf(fmaf(a0, inv, bb0.x), 0.f),
                                               fmaxf(fmaf(a1, inv, bb0.y), 0.f));
                __half2 p1 = __floats2half2_rn(fmaxf(fmaf(a2, inv, bb0.z), 0.f),
                                               fmaxf(fmaf(a3, inv, bb0.w), 0.f));
                __half2 p2 = __floats2half2_rn(fmaxf(fmaf(a4, inv, bb1.x), 0.f),
                                               fmaxf(fmaf(a5, inv, bb1.y), 0.f));
                __half2 p3 = __floats2half2_rn(fmaxf(fmaf(a6, inv, bb1.z), 0.f),
                                               fmaxf(fmaf(a7, inv, bb1.w), 0.f));
                u.x = *reinterpret_cast<unsigned*>(&p0);
                u.y = *reinterpret_cast<unsigned*>(&p1);
                u.z = *reinterpret_cast<unsigned*>(&p2);
                u.w = *reinterpret_cast<unsigned*>(&p3);
            } else {
                u = make_uint4(0u, 0u, 0u, 0u);
            }
            *reinterpret_cast<uint4*>(&As[row * LDA + l * 8]) = u;
        }
    }
    __syncthreads();

    // mma: 128x32x64
    wmma::fragment<wmma::accumulator, 16, 16, 16, float> c[NF];
#pragma unroll
    for (int j = 0; j < NF; j++) wmma::fill_fragment(c[j], 0.f);
#pragma unroll
    for (int k0 = 0; k0 < 64; k0 += 16) {
        wmma::fragment<wmma::matrix_a, 16, 16, 16, __half, wmma::row_major> a;
        wmma::load_matrix_sync(a, &As[wid * 16 * LDA + k0], LDA);
#pragma unroll
        for (int j = 0; j < NF; j++) {
            wmma::fragment<wmma::matrix_b, 16, 16, 16, __half, wmma::row_major> b;
            wmma::load_matrix_sync(b, &Bs[k0 * LDB + j * 16], LDB);
            wmma::mma_sync(c[j], a, b, c[j]);
        }
    }
    __syncthreads();
#pragma unroll
    for (int j = 0; j < NF; j++)
        wmma::store_matrix_sync(&Cs[wid * 16 * LDC + j * 16], c[j], LDC, wmma::mem_row_major);
    __syncthreads();

    // gemm2 epilogue -> g_h2h + layer2 logits
    int tx = tid % 8, ty = tid / 8;     // CG=8, RPT=4, TXH=2
    float4 sa = *reinterpret_cast<const float4*>(&asrc2[tx * 4]);
    float4 da = *reinterpret_cast<const float4*>(&adst2[tx * 4]);
    int h2 = tx >> 1;
#pragma unroll
    for (int i = 0; i < 4; i++) {
        int row = ty * 4 + i;
        int r = rbase + row;
        float4 acc = *reinterpret_cast<const float4*>(&Cs[row * LDC + tx * 4]);
        float ps = acc.x * sa.x + acc.y * sa.y + acc.z * sa.z + acc.w * sa.w;
        float pd = acc.x * da.x + acc.y * da.y + acc.z * da.z + acc.w * da.w;
        ps += __shfl_xor_sync(0xffffffffu, ps, 1);
        pd += __shfl_xor_sync(0xffffffffu, pd, 1);
        if (r < n) {
            __half2 ha = __floats2half2_rn(acc.x, acc.y);
            __half2 hb = __floats2half2_rn(acc.z, acc.w);
            uint2 u;
            u.x = *reinterpret_cast<unsigned*>(&ha);
            u.y = *reinterpret_cast<unsigned*>(&hb);
            *reinterpret_cast<uint2*>(&g_h2h[r * 32 + tx * 4]) = u;
            if ((tx & 1) == 0) {
                g_als2[r * 4 + h2] = ps;
                g_ald2[r * 4 + h2] = pd;
            }
        }
    }
}

// ---------------- layer2 aggregation + log_softmax -> out ----------------
__global__ void k_agg2(const float* __restrict__ b2, float* __restrict__ out_arg, int n) {
    const int LPE = 4, SUBS = 8;
    int warp = (blockIdx.x * blockDim.x + threadIdx.x) >> 5;
    if (warp >= n) return;
    int d = warp;
    int lane = threadIdx.x & 31;
    int sub = lane / LPE;
    int l = lane % LPE;
    int h = l;                           // C=8 -> one head per lane-octet
    float ald_v = g_ald2[d * 4 + h];
    int off0 = g_off[d], off1 = g_off[d + 1];
    float a0 = 0.f, a1 = 0.f, a2 = 0.f, a3 = 0.f;
    float a4 = 0.f, a5 = 0.f, a6 = 0.f, a7 = 0.f;
    float esum = 0.f;
    for (int i = off0 + sub; i < off1; i += SUBS) {
        int s = g_esrc[i];
        float lg = g_als2[s * 4 + h] + ald_v;
        lg = (lg >= 0.f) ? lg : NEG * lg;
        float ev = __expf(lg);
        esum += ev;
        uint4 raw = *reinterpret_cast<const uint4*>(&g_h2h[s * 32 + l * 8]);
        float2 f0 = __half22float2(*reinterpret_cast<__half2*>(&raw.x));
        float2 f1 = __half22float2(*reinterpret_cast<__half2*>(&raw.y));
        float2 f2 = __half22float2(*reinterpret_cast<__half2*>(&raw.z));
        float2 f3 = __half22float2(*reinterpret_cast<__half2*>(&raw.w));
        a0 = fmaf(ev, f0.x, a0); a1 = fmaf(ev, f0.y, a1);
        a2 = fmaf(ev, f1.x, a2); a3 = fmaf(ev, f1.y, a3);
        a4 = fmaf(ev, f2.x, a4); a5 = fmaf(ev, f2.y, a5);
        a6 = fmaf(ev, f3.x, a6); a7 = fmaf(ev, f3.y, a7);
    }
#pragma unroll
    for (int ofs = LPE; ofs < 32; ofs <<= 1) {
        a0 += __shfl_xor_sync(0xffffffffu, a0, ofs);
        a1 += __shfl_xor_sync(0xffffffffu, a1, ofs);
        a2 += __shfl_xor_sync(0xffffffffu, a2, ofs);
        a3 += __shfl_xor_sync(0xffffffffu, a3, ofs);
        a4 += __shfl_xor_sync(0xffffffffu, a4, ofs);
        a5 += __shfl_xor_sync(0xffffffffu, a5, ofs);
        a6 += __shfl_xor_sync(0xffffffffu, a6, ofs);
        a7 += __shfl_xor_sync(0xffffffffu, a7, ofs);
        esum += __shfl_xor_sync(0xffffffffu, esum, ofs);
    }
    float inv = 1.f / (esum + EPSV);
    float4 b0 = reinterpret_cast<const float4*>(b2)[l * 2];
    float4 b1v = reinterpret_cast<const float4*>(b2)[l * 2 + 1];
    float r0 = fmaf(a0, inv, b0.x), r1 = fmaf(a1, inv, b0.y);
    float r2 = fmaf(a2, inv, b0.z), r3 = fmaf(a3, inv, b0.w);
    float r4 = fmaf(a4, inv, b1v.x), r5 = fmaf(a5, inv, b1v.y);
    float r6 = fmaf(a6, inv, b1v.z), r7 = fmaf(a7, inv, b1v.w);
    float m = fmaxf(fmaxf(fmaxf(r0, r1), fmaxf(r2, r3)),
                    fmaxf(fmaxf(r4, r5), fmaxf(r6, r7)));
#pragma unroll
    for (int ofs = 1; ofs < LPE; ofs <<= 1)
        m = fmaxf(m, __shfl_xor_sync(0xffffffffu, m, ofs));
    float ssum = expf(r0 - m) + expf(r1 - m) + expf(r2 - m) + expf(r3 - m)
               + expf(r4 - m) + expf(r5 - m) + expf(r6 - m) + expf(r7 - m);
#pragma unroll
    for (int ofs = 1; ofs < LPE; ofs <<= 1)
        ssum += __shfl_xor_sync(0xffffffffu, ssum, ofs);
    float ls = m + logf(ssum);
    if (sub == 0) {
        float4 o0 = make_float4(r0 - ls, r1 - ls, r2 - ls, r3 - ls);
        float4 o1 = make_float4(r4 - ls, r5 - ls, r6 - ls, r7 - ls);
        *reinterpret_cast<float4*>(&out_arg[d * 32 + l * 8]) = o0;
        *reinterpret_cast<float4*>(&out_arg[d * 32 + l * 8 + 4]) = o1;
    }
}

// ---------------- launch ----------------
static inline int cdiv(long long a, int b) { return (int)((a + b - 1) / b); }

extern "C" void kernel_launch(void* const* d_in, const int* in_sizes, int n_in,
                              void* d_out, int out_size) {
    const float* x      = (const float*)d_in[0];
    const int*   ei32   = (const int*)d_in[1];
    const float* W1     = (const float*)d_in[2];
    const float* a_src1 = (const float*)d_in[3];
    const float* a_dst1 = (const float*)d_in[4];
    const float* b1     = (const float*)d_in[5];
    const float* W2     = (const float*)d_in[6];
    const float* a_src2 = (const float*)d_in[7];
    const float* a_dst2 = (const float*)d_in[8];
    const float* b2     = (const float*)d_in[9];
    float* out = (float*)d_out;

    const int n = in_sizes[0] / 128;   // 50000
    const int E = 800000;
    const int Etot = E + n;            // 850000
    const int B = 256;

    static cudaStream_t s2 = nullptr;
    static cudaEvent_t evF = nullptr, evJ = nullptr;
    if (!s2) {
        cudaStreamCreateWithFlags(&s2, cudaStreamNonBlocking);
        cudaEventCreateWithFlags(&evF, cudaEventDisableTiming);
        cudaEventCreateWithFlags(&evJ, cudaEventDisableTiming);
    }

    // fork: CSR build (full-chip kernels) on s2, gemm1 on main stream
    cudaEventRecord(evF, 0);
    cudaStreamWaitEvent(s2, evF, 0);
    k_build_hist<<<cdiv(Etot / 2, B), B, 0, s2>>>(ei32, E, Etot);
    k_scan<<<NBLK, SCB, 0, s2>>>(n, Etot);
    k_fill<<<cdiv(Etot / 2, B), B, 0, s2>>>(ei32, E, Etot);
    cudaEventRecord(evJ, s2);

    k_gemm1<<<cdiv(n, 128), 256>>>(x, W1, a_src1, a_dst1, n);

    cudaStreamWaitEvent(0, evJ, 0);

    k_agg1_gemm2<<<cdiv(n, 128), 256>>>(W2, b1, a_src2, a_dst2, n);
    k_agg2<<<cdiv((long long)n * 32, B), B>>>(b2, out, n);
}

// round 17
// speedup vs baseline: 1.1114x; 1.1114x over previous
#include <cuda_runtime.h>
#include <cuda_fp16.h>
#include <mma.h>
#include <math.h>

using namespace nvcuda;

#define NN 50000
#define EE 800000
#define ETOT (EE + NN)
#define NH 4
#define NEG 0.2f
#define EPSV 1e-16f
#define SCB 1024
#define NBLK ((NN + SCB - 1) / SCB)   // 49
#define FLAGB 0x40000000

// ---------------- scratch (device globals; no allocation) ----------------
// NOTE: never pass these as kernel args from host code (host shadow symbol bug).
__device__ __half g_h1h[NN * 64];   // gemm out in fp16 (gather-only buffer)
__device__ __half g_bufh[NN * 64];  // layer1 relu'd aggregated features (fp16)
__device__ float  g_als[NN * NH];
__device__ float  g_ald[NN * NH];
__device__ int    g_cnt[NN];        // zeroed at start; re-zeroed by k_scan each run
__device__ int    g_off[NN + 1];
__device__ int    g_cur[NN];
__device__ int    g_esrc[ETOT];
__device__ int    g_bsum[NBLK];     // lookback aggregates; re-zeroed by k_fill each run

__device__ __forceinline__ int detect_is64_block(const int* __restrict__ ei32, int* s_flag) {
    if (threadIdx.x == 0) {
        int all0 = 1;
        for (int j = 0; j < 32; j++)
            if (ei32[2 * j + 1] != 0) { all0 = 0; break; }
        *s_flag = all0;
    }
    __syncthreads();
    return *s_flag;
}

// ---------------- dst histogram, 2 edges/thread (full-chip) ----------------
__global__ void k_build_hist(const int* __restrict__ ei32, int E, int Etot) {
    __shared__ int s64;
    int is64 = detect_is64_block(ei32, &s64);
    int e = (blockIdx.x * blockDim.x + threadIdx.x) * 2;
    if (e >= Etot) return;
    int d0, d1;
    if (e < E) {                       // pairs never straddle (E even)
        if (is64) { int4 v = *reinterpret_cast<const int4*>(&ei32[2 * (E + e)]); d0 = v.x; d1 = v.z; }
        else      { int2 v = *reinterpret_cast<const int2*>(&ei32[E + e]);       d0 = v.x; d1 = v.y; }
    } else { d0 = e - E; d1 = e + 1 - E; }
    atomicAdd(&g_cnt[d0], 1);
    atomicAdd(&g_cnt[d1], 1);
}

// ---------------- single-pass decoupled-lookback exclusive scan ----------------
__global__ void k_scan(int n, int Etot) {
    __shared__ int ws[32];
    __shared__ int s_pre;
    int t = threadIdx.x;
    int bid = blockIdx.x;
    int i = bid * SCB + t;
    int v = (i < n) ? g_cnt[i] : 0;
    int x = v;
#pragma unroll
    for (int ofs = 1; ofs < 32; ofs <<= 1) {
        int u = __shfl_up_sync(0xffffffffu, x, ofs);
        if ((t & 31) >= ofs) x += u;
    }
    if ((t & 31) == 31) ws[t >> 5] = x;
    __syncthreads();
    if (t < 32) {
        int y = ws[t];
#pragma unroll
        for (int ofs = 1; ofs < 32; ofs <<= 1) {
            int u = __shfl_up_sync(0xffffffffu, y, ofs);
            if (t >= ofs) y += u;
        }
        ws[t] = y;
    }
    __syncthreads();
    int base = (t >= 32) ? ws[(t >> 5) - 1] : 0;
    int incl = x + base;
    if (t == 0)
        atomicExch(&g_bsum[bid], ws[31] | FLAGB);
    if (t < 32) {
        int pre = 0;
        for (int b0 = 0; b0 < bid; b0 += 32) {
            int j = b0 + t;
            int vv = 0;
            if (j < bid) {
                while (((vv = atomicAdd(&g_bsum[j], 0)) & FLAGB) == 0) { }
                vv &= ~FLAGB;
            }
#pragma unroll
            for (int ofs = 16; ofs; ofs >>= 1)
                vv += __shfl_xor_sync(0xffffffffu, vv, ofs);
            pre += vv;
        }
        if (t == 0) s_pre = pre;
    }
    __syncthreads();
    int off = incl - v + s_pre;
    if (i < n) {
        g_off[i] = off;
        g_cur[i] = off;
        g_cnt[i] = 0;
    }
    if (i == 0) g_off[n] = Etot;
}

// ---------------- bucket-fill, 2 edges/thread (full-chip, + g_bsum reset) ----------------
__global__ void k_fill(const int* __restrict__ ei32, int E, int Etot) {
    __shared__ int s64;
    int is64 = detect_is64_block(ei32, &s64);
    if (blockIdx.x == 0 && threadIdx.x < NBLK) g_bsum[threadIdx.x] = 0;
    int e = (blockIdx.x * blockDim.x + threadIdx.x) * 2;
    if (e >= Etot) return;
    int s0, s1, d0, d1;
    if (e < E) {
        if (is64) {
            int4 sv = *reinterpret_cast<const int4*>(&ei32[2 * e]);
            int4 dv = *reinterpret_cast<const int4*>(&ei32[2 * (E + e)]);
            s0 = sv.x; s1 = sv.z; d0 = dv.x; d1 = dv.z;
        } else {
            int2 sv = *reinterpret_cast<const int2*>(&ei32[e]);
            int2 dv = *reinterpret_cast<const int2*>(&ei32[E + e]);
            s0 = sv.x; s1 = sv.y; d0 = dv.x; d1 = dv.y;
        }
    } else { s0 = d0 = e - E; s1 = d1 = e + 1 - E; }
    int p0 = atomicAdd(&g_cur[d0], 1);
    g_esrc[p0] = s0;
    int p1 = atomicAdd(&g_cur[d1], 1);
    g_esrc[p1] = s1;
}

// ---------------- wmma fp16 GEMM (R13 config + launch_bounds) ----------------
// 128 rows x 256 threads, KT chunks, static smem with C overlay.
// LAYER=1: A = x (fp32 arg), KTOT=128, COLS=64, KT=64.
// LAYER=2: A = g_bufh (fp16), KTOT=64, COLS=32, KT=32.
// Epilogue: fp16 feature store to g_h1h + fused per-head logits.
template <int KTOT, int COLS, int LAYER>
__global__ void __launch_bounds__(256, 4)
k_gemm_wmma(const float* __restrict__ A_arg,
            const float* __restrict__ W,
            const float* __restrict__ asrc,
            const float* __restrict__ adst, int n) {
    const int KT  = (KTOT > 64) ? 64 : KTOT >= 64 ? (LAYER == 1 ? 64 : 32) : KTOT;
    const int KTC = (LAYER == 1) ? 64 : 32;
    const int NCH = KTOT / KTC;
    const int LDA = KTC + 8;
    const int LDB = COLS + 8;
    const int LDC = COLS + 8;
    const int NF  = COLS / 16;
    const int ABBYTES = 128 * LDA * 2 + KTOT * LDB * 2;
    const int CBYTES  = 128 * LDC * 4;
    __shared__ __align__(16) char sraw[ABBYTES > CBYTES ? ABBYTES : CBYTES];
    __half* As = reinterpret_cast<__half*>(sraw);
    __half* Bs = reinterpret_cast<__half*>(sraw + 128 * LDA * 2);
    float*  Cs = reinterpret_cast<float*>(sraw);
    (void)KT;

    int tid = threadIdx.x;
    int w = tid >> 5;
    int rbase = blockIdx.x * 128;

    // load full W (KTOT x COLS) fp32 -> fp16
    const int B4 = KTOT * COLS / 4;
#pragma unroll
    for (int j = 0; j < (B4 + 255) / 256; j++) {
        int idx = tid + j * 256;
        if (idx < B4) {
            int row = idx / (COLS / 4), c4 = idx % (COLS / 4);
            float4 v = *reinterpret_cast<const float4*>(&W[row * COLS + c4 * 4]);
            __half2 h0 = __floats2half2_rn(v.x, v.y);
            __half2 h1 = __floats2half2_rn(v.z, v.w);
            uint2 u;
            u.x = *reinterpret_cast<unsigned*>(&h0);
            u.y = *reinterpret_cast<unsigned*>(&h1);
            *reinterpret_cast<uint2*>(&Bs[row * LDB + c4 * 4]) = u;
        }
    }

    wmma::fragment<wmma::accumulator, 16, 16, 16, float> c[NF];
#pragma unroll
    for (int j = 0; j < NF; j++) wmma::fill_fragment(c[j], 0.f);

#pragma unroll
    for (int ch = 0; ch < NCH; ch++) {
        __syncthreads();
        if (LAYER == 1) {
            const int A4 = 128 * KTC / 4;
#pragma unroll
            for (int j = 0; j < A4 / 256; j++) {
                int idx = tid + j * 256;
                int row = idx / (KTC / 4), k4 = idx % (KTC / 4);
                int rg = rbase + row;
                if (rg >= n) rg = n - 1;
                float4 v = *reinterpret_cast<const float4*>(&A_arg[rg * KTOT + ch * KTC + k4 * 4]);
                __half2 h0 = __floats2half2_rn(v.x, v.y);
                __half2 h1 = __floats2half2_rn(v.z, v.w);
                uint2 u;
                u.x = *reinterpret_cast<unsigned*>(&h0);
                u.y = *reinterpret_cast<unsigned*>(&h1);
                *reinterpret_cast<uint2*>(&As[row * LDA + k4 * 4]) = u;
            }
        } else {
            const int A8 = 128 * KTC / 8;
#pragma unroll
            for (int j = 0; j < A8 / 256; j++) {
                int idx = tid + j * 256;
                int row = idx / (KTC / 8), k8 = idx % (KTC / 8);
                int rg = rbase + row;
                if (rg >= n) rg = n - 1;
                uint4 v = *reinterpret_cast<const uint4*>(&g_bufh[rg * 64 + ch * KTC + k8 * 8]);
                *reinterpret_cast<uint4*>(&As[row * LDA + k8 * 8]) = v;
            }
        }
        __syncthreads();
#pragma unroll
        for (int k0 = 0; k0 < KTC; k0 += 16) {
            wmma::fragment<wmma::matrix_a, 16, 16, 16, __half, wmma::row_major> a;
            wmma::load_matrix_sync(a, &As[w * 16 * LDA + k0], LDA);
#pragma unroll
            for (int j = 0; j < NF; j++) {
                wmma::fragment<wmma::matrix_b, 16, 16, 16, __half, wmma::row_major> b;
                wmma::load_matrix_sync(b, &Bs[(ch * KTC + k0) * LDB + j * 16], LDB);
                wmma::mma_sync(c[j], a, b, c[j]);
            }
        }
    }
    __syncthreads();
#pragma unroll
    for (int j = 0; j < NF; j++)
        wmma::store_matrix_sync(&Cs[w * 16 * LDC + j * 16], c[j], LDC, wmma::mem_row_major);
    __syncthreads();

    // epilogue
    const int CG  = COLS / 4;
    const int RPT = 128 / (256 / CG);
    const int C   = COLS / NH;
    const int TXH = C / 4;
    int tx = tid % CG, ty = tid / CG;
    float4 sa = *reinterpret_cast<const float4*>(&asrc[tx * 4]);
    float4 da = *reinterpret_cast<const float4*>(&adst[tx * 4]);
    int h = tx / TXH;
#pragma unroll
    for (int i = 0; i < RPT; i++) {
        int row = ty * RPT + i;
        int r = rbase + row;
        float4 acc = *reinterpret_cast<const float4*>(&Cs[row * LDC + tx * 4]);
        float ps = acc.x * sa.x + acc.y * sa.y + acc.z * sa.z + acc.w * sa.w;
        float pd = acc.x * da.x + acc.y * da.y + acc.z * da.z + acc.w * da.w;
#pragma unroll
        for (int ofs = 1; ofs < TXH; ofs <<= 1) {
            ps += __shfl_xor_sync(0xffffffffu, ps, ofs);
            pd += __shfl_xor_sync(0xffffffffu, pd, ofs);
        }
        if (r < n) {
            __half2 ha = __floats2half2_rn(acc.x, acc.y);
            __half2 hb = __floats2half2_rn(acc.z, acc.w);
            uint2 u;
            u.x = *reinterpret_cast<unsigned*>(&ha);
            u.y = *reinterpret_cast<unsigned*>(&hb);
            *reinterpret_cast<uint2*>(&g_h1h[r * COLS + tx * 4]) = u;
            if ((tx & (TXH - 1)) == 0) {
                g_als[r * 4 + h] = ps;
                g_ald[r * 4 + h] = pd;
            }
        }
    }
}

// ---------------- CSR aggregation: one warp per dst node, fp16 gather ----------------
template <int LAYER>
__global__ void k_agg_csr(const float* __restrict__ bias, float* __restrict__ out_arg, int n) {
    const int HC   = (LAYER == 1) ? 64 : 32;
    const int C    = HC / NH;
    const int LPE  = HC / 8;
    const int SUBS = 32 / LPE;
    int warp = (blockIdx.x * blockDim.x + threadIdx.x) >> 5;
    if (warp >= n) return;
    int d = warp;
    int lane = threadIdx.x & 31;
    int sub = lane / LPE;
    int l = lane % LPE;
    int h = (l * 8) / C;
    float ald_v = g_ald[d * 4 + h];
    int off0 = g_off[d], off1 = g_off[d + 1];
    float a0 = 0.f, a1 = 0.f, a2 = 0.f, a3 = 0.f;
    float a4 = 0.f, a5 = 0.f, a6 = 0.f, a7 = 0.f;
    float esum = 0.f;
    for (int i = off0 + sub; i < off1; i += SUBS) {
        int s = g_esrc[i];
        float lg = g_als[s * 4 + h] + ald_v;
        lg = (lg >= 0.f) ? lg : NEG * lg;
        float ev = __expf(lg);
        esum += ev;
        uint4 raw = *reinterpret_cast<const uint4*>(&g_h1h[s * HC + l * 8]);
        float2 f0 = __half22float2(*reinterpret_cast<__half2*>(&raw.x));
        float2 f1 = __half22float2(*reinterpret_cast<__half2*>(&raw.y));
        float2 f2 = __half22float2(*reinterpret_cast<__half2*>(&raw.z));
        float2 f3 = __half22float2(*reinterpret_cast<__half2*>(&raw.w));
        a0 = fmaf(ev, f0.x, a0); a1 = fmaf(ev, f0.y, a1);
        a2 = fmaf(ev, f1.x, a2); a3 = fmaf(ev, f1.y, a3);
        a4 = fmaf(ev, f2.x, a4); a5 = fmaf(ev, f2.y, a5);
        a6 = fmaf(ev, f3.x, a6); a7 = fmaf(ev, f3.y, a7);
    }
#pragma unroll
    for (int ofs = LPE; ofs < 32; ofs <<= 1) {
        a0 += __shfl_xor_sync(0xffffffffu, a0, ofs);
        a1 += __shfl_xor_sync(0xffffffffu, a1, ofs);
        a2 += __shfl_xor_sync(0xffffffffu, a2, ofs);
        a3 += __shfl_xor_sync(0xffffffffu, a3, ofs);
        a4 += __shfl_xor_sync(0xffffffffu, a4, ofs);
        a5 += __shfl_xor_sync(0xffffffffu, a5, ofs);
        a6 += __shfl_xor_sync(0xffffffffu, a6, ofs);
        a7 += __shfl_xor_sync(0xffffffffu, a7, ofs);
        esum += __shfl_xor_sync(0xffffffffu, esum, ofs);
    }
    float inv = 1.f / (esum + EPSV);
    float4 b0 = reinterpret_cast<const float4*>(bias)[l * 2];
    float4 b1v = reinterpret_cast<const float4*>(bias)[l * 2 + 1];
    float r0 = fmaf(a0, inv, b0.x), r1 = fmaf(a1, inv, b0.y);
    float r2 = fmaf(a2, inv, b0.z), r3 = fmaf(a3, inv, b0.w);
    float r4 = fmaf(a4, inv, b1v.x), r5 = fmaf(a5, inv, b1v.y);
    float r6 = fmaf(a6, inv, b1v.z), r7 = fmaf(a7, inv, b1v.w);
    if (LAYER == 1) {
        if (sub == 0) {
            __half2 p0 = __floats2half2_rn(fmaxf(r0, 0.f), fmaxf(r1, 0.f));
            __half2 p1 = __floats2half2_rn(fmaxf(r2, 0.f), fmaxf(r3, 0.f));
            __half2 p2 = __floats2half2_rn(fmaxf(r4, 0.f), fmaxf(r5, 0.f));
            __half2 p3 = __floats2half2_rn(fmaxf(r6, 0.f), fmaxf(r7, 0.f));
            uint4 u;
            u.x = *reinterpret_cast<unsigned*>(&p0);
            u.y = *reinterpret_cast<unsigned*>(&p1);
            u.z = *reinterpret_cast<unsigned*>(&p2);
            u.w = *reinterpret_cast<unsigned*>(&p3);
            *reinterpret_cast<uint4*>(&g_bufh[d * 64 + l * 8]) = u;
        }
    } else {
        float m = fmaxf(fmaxf(fmaxf(r0, r1), fmaxf(r2, r3)),
                        fmaxf(fmaxf(r4, r5), fmaxf(r6, r7)));
#pragma unroll
        for (int ofs = 1; ofs < LPE; ofs <<= 1)
            m = fmaxf(m, __shfl_xor_sync(0xffffffffu, m, ofs));
        float ssum = expf(r0 - m) + expf(r1 - m) + expf(r2 - m) + expf(r3 - m)
                   + expf(r4 - m) + expf(r5 - m) + expf(r6 - m) + expf(r7 - m);
#pragma unroll
        for (int ofs = 1; ofs < LPE; ofs <<= 1)
            ssum += __shfl_xor_sync(0xffffffffu, ssum, ofs);
        float ls = m + logf(ssum);
        if (sub == 0) {
            float4 o0 = make_float4(r0 - ls, r1 - ls, r2 - ls, r3 - ls);
            float4 o1 = make_float4(r4 - ls, r5 - ls, r6 - ls, r7 - ls);
            *reinterpret_cast<float4*>(&out_arg[d * 32 + l * 8]) = o0;
            *reinterpret_cast<float4*>(&out_arg[d * 32 + l * 8 + 4]) = o1;
        }
    }
}

// ---------------- launch ----------------
static inline int cdiv(long long a, int b) { return (int)((a + b - 1) / b); }

extern "C" void kernel_launch(void* const* d_in, const int* in_sizes, int n_in,
                              void* d_out, int out_size) {
    const float* x      = (const float*)d_in[0];
    const int*   ei32   = (const int*)d_in[1];
    const float* W1     = (const float*)d_in[2];
    const float* a_src1 = (const float*)d_in[3];
    const float* a_dst1 = (const float*)d_in[4];
    const float* b1     = (const float*)d_in[5];
    const float* W2     = (const float*)d_in[6];
    const float* a_src2 = (const float*)d_in[7];
    const float* a_dst2 = (const float*)d_in[8];
    const float* b2     = (const float*)d_in[9];
    float* out = (float*)d_out;

    const int n = in_sizes[0] / 128;   // 50000
    const int E = 800000;
    const int Etot = E + n;            // 850000
    const int B = 256;

    static cudaStream_t s2 = nullptr;
    static cudaEvent_t evF = nullptr, evJ = nullptr;
    if (!s2) {
        cudaStreamCreateWithFlags(&s2, cudaStreamNonBlocking);
        cudaEventCreateWithFlags(&evF, cudaEventDisableTiming);
        cudaEventCreateWithFlags(&evJ, cudaEventDisableTiming);
    }

    // fork: CSR build (full-chip kernels) on s2, gemm1 on main stream
    cudaEventRecord(evF, 0);
    cudaStreamWaitEvent(s2, evF, 0);
    k_build_hist<<<cdiv(Etot / 2, B), B, 0, s2>>>(ei32, E, Etot);
    k_scan<<<NBLK, SCB, 0, s2>>>(n, Etot);
    k_fill<<<cdiv(Etot / 2, B), B, 0, s2>>>(ei32, E, Etot);
    cudaEventRecord(evJ, s2);

    k_gemm_wmma<128, 64, 1><<<cdiv(n, 128), 256>>>(x, W1, a_src1, a_dst1, n);

    cudaStreamWaitEvent(0, evJ, 0);

    k_agg_csr<1><<<cdiv((long long)n * 32, B), B>>>(b1, nullptr, n);
    k_gemm_wmma<64, 32, 2><<<cdiv(n, 128), 256>>>(nullptr, W2, a_src2, a_dst2, n);
    k_agg_csr<2><<<cdiv((long long)n * 32, B), B>>>(b2, out, n);
}